// round 14
// baseline (speedup 1.0000x reference)
#include <cuda_runtime.h>
#include <cuda_bf16.h>
#include <math.h>
#include <stdint.h>

// Problem constants
#define NT     4096        // B*S tokens
#define DMODEL 1024
#define NHEAD  16
#define HD     64
#define SEQ    2048
#define BATCH  2
#define KWRD   (DMODEL / 2)

// Scratch (no cudaMalloc allowed)
__device__ float g_Q[(size_t)NT * DMODEL];
__device__ float g_K[(size_t)NT * DMODEL];
__device__ float g_V[(size_t)NT * DMODEL];
__device__ float g_A[(size_t)NT * DMODEL];

// Pre-split bf16 hi/lo buffers, FRAGMENT-ORDERED:
// A' [mtile16][k16][lane32][4 words], B' [ntile64][k16][lane32][16 words]
__device__ uint32_t g_xh[(size_t)NT * KWRD],  g_xl[(size_t)NT * KWRD];
__device__ uint32_t g_ah[(size_t)NT * KWRD],  g_al[(size_t)NT * KWRD];
__device__ uint32_t g_wqh[(size_t)KWRD * DMODEL], g_wql[(size_t)KWRD * DMODEL];
__device__ uint32_t g_wkh[(size_t)KWRD * DMODEL], g_wkl[(size_t)KWRD * DMODEL];
__device__ uint32_t g_wvh[(size_t)KWRD * DMODEL], g_wvl[(size_t)KWRD * DMODEL];
__device__ uint32_t g_woh[(size_t)KWRD * DMODEL], g_wol[(size_t)KWRD * DMODEL];

__device__ __forceinline__ float f2tf(float x) {
    uint32_t r; asm("cvt.rna.tf32.f32 %0, %1;" : "=r"(r) : "f"(x));
    return __uint_as_float(r);
}

__device__ __forceinline__ void mma_tf32(float c[4], uint32_t a0, uint32_t a1,
                                         uint32_t a2, uint32_t a3,
                                         uint32_t b0, uint32_t b1) {
    asm volatile(
        "mma.sync.aligned.m16n8k8.row.col.f32.tf32.tf32.f32 "
        "{%0,%1,%2,%3}, {%4,%5,%6,%7}, {%8,%9}, {%0,%1,%2,%3};\n"
        : "+f"(c[0]), "+f"(c[1]), "+f"(c[2]), "+f"(c[3])
        : "r"(a0), "r"(a1), "r"(a2), "r"(a3), "r"(b0), "r"(b1));
}

__device__ __forceinline__ void mma_bf16(float c[4], uint32_t a0, uint32_t a1,
                                         uint32_t a2, uint32_t a3,
                                         uint32_t b0, uint32_t b1) {
    asm volatile(
        "mma.sync.aligned.m16n8k16.row.col.f32.bf16.bf16.f32 "
        "{%0,%1,%2,%3}, {%4,%5,%6,%7}, {%8,%9}, {%0,%1,%2,%3};\n"
        : "+f"(c[0]), "+f"(c[1]), "+f"(c[2]), "+f"(c[3])
        : "r"(a0), "r"(a1), "r"(a2), "r"(a3), "r"(b0), "r"(b1));
}

__device__ __forceinline__ uint32_t split_pack(float x, float y, uint32_t& lo_w) {
    __nv_bfloat16 hx = __float2bfloat16(x);
    __nv_bfloat16 hy = __float2bfloat16(y);
    __nv_bfloat16 lx = __float2bfloat16(x - __bfloat162float(hx));
    __nv_bfloat16 ly = __float2bfloat16(y - __bfloat162float(hy));
    lo_w = ((uint32_t)__bfloat16_as_ushort(ly) << 16) | __bfloat16_as_ushort(lx);
    return ((uint32_t)__bfloat16_as_ushort(hy) << 16) | __bfloat16_as_ushort(hx);
}

__device__ __forceinline__ void cpasync16(uint32_t s, const void* g) {
    asm volatile("cp.async.cg.shared.global [%0], [%1], 16;"
                 :: "r"(s), "l"(g) : "memory");
}

// ---------------------------------------------------------------------------
// Split into fragment-ordered layouts.
// A': word (mt,ks,lane,w): w0=(m=g,kw=t) w1=(g+8,t) w2=(g,t+4) w3=(g+8,t+4)
// B': word (ntile,ks,lane,w): nt=w&7, kw=t+4*(w>>3), n=ntile*64+nt*8+g
// ---------------------------------------------------------------------------
__global__ void split_rowsF(const float* __restrict__ X, uint32_t* __restrict__ H,
                            uint32_t* __restrict__ L, int nthreads)
{
    int j = blockIdx.x * blockDim.x + threadIdx.x;
    if (j >= nthreads) return;
    int lane = j & 31, ks = (j >> 5) & 63, mt = j >> 11;
    int g = lane >> 2, t = lane & 3;
    const float* r0 = X + (size_t)(mt * 16 + g) * DMODEL + ks * 16;
    const float* r1 = r0 + 8 * DMODEL;
    uint4 hi, lo;
    hi.x = split_pack(r0[2 * t],     r0[2 * t + 1], lo.x);
    hi.y = split_pack(r1[2 * t],     r1[2 * t + 1], lo.y);
    hi.z = split_pack(r0[2 * t + 8], r0[2 * t + 9], lo.z);
    hi.w = split_pack(r1[2 * t + 8], r1[2 * t + 9], lo.w);
    ((uint4*)H)[j] = hi;
    ((uint4*)L)[j] = lo;
}

__global__ void split_cols4F(
    const float* __restrict__ W0, const float* __restrict__ W1,
    const float* __restrict__ W2, const float* __restrict__ W3,
    uint32_t* __restrict__ H0, uint32_t* __restrict__ L0,
    uint32_t* __restrict__ H1, uint32_t* __restrict__ L1,
    uint32_t* __restrict__ H2, uint32_t* __restrict__ L2,
    uint32_t* __restrict__ H3, uint32_t* __restrict__ L3,
    int nthreads)
{
    const int wsel = blockIdx.y;
    const float* W = (wsel == 0) ? W0 : (wsel == 1) ? W1 : (wsel == 2) ? W2 : W3;
    uint32_t* H = (wsel == 0) ? H0 : (wsel == 1) ? H1 : (wsel == 2) ? H2 : H3;
    uint32_t* L = (wsel == 0) ? L0 : (wsel == 1) ? L1 : (wsel == 2) ? L2 : L3;
    int j = blockIdx.x * blockDim.x + threadIdx.x;
    if (j >= nthreads) return;
    int lane = j & 31, ks = (j >> 5) & 63, ntile = j >> 11;
    int g = lane >> 2, t = lane & 3;
    uint32_t h[16], l[16];
    #pragma unroll
    for (int w = 0; w < 16; w++) {
        int nt = w & 7;
        int kw = t + ((w >> 3) << 2);
        int k0 = ks * 16 + 2 * kw;
        int n  = ntile * 64 + nt * 8 + g;
        h[w] = split_pack(W[(size_t)k0 * DMODEL + n],
                          W[(size_t)(k0 + 1) * DMODEL + n], l[w]);
    }
    #pragma unroll
    for (int q = 0; q < 4; q++) {
        ((uint4*)H)[j * 4 + q] = make_uint4(h[q*4], h[q*4+1], h[q*4+2], h[q*4+3]);
        ((uint4*)L)[j * 4 + q] = make_uint4(l[q*4], l[q*4+1], l[q*4+2], l[q*4+3]);
    }
}

// ---------------------------------------------------------------------------
// 3xBF16 GEMM on fragment-ordered operands. 128 threads, block 128x128,
// warp tile 64x64, BK=32, 2-stage cp.async. All frag loads are LDS.128.
// Stage layout (words): Ah[0..2047] Al[2048..4095] Bh[4096..6143] Bl[6144..8191]
// ---------------------------------------------------------------------------
#define STG_WORDS 8192
#define GEMM_SMEM (2 * STG_WORDS * 4)    // 65536 bytes

__global__ __launch_bounds__(128) void gemm_bf16p(
    const uint32_t* __restrict__ Ah, const uint32_t* __restrict__ Al,
    const uint32_t* __restrict__ Bh, const uint32_t* __restrict__ Bl,
    float* __restrict__ C, int M, int N, int K, int round_out)
{
    extern __shared__ uint32_t smw[];
    const uint32_t sbase = (uint32_t)__cvta_generic_to_shared(smw);

    const int tid  = threadIdx.x;
    const int lane = tid & 31;
    const int warp = tid >> 5;
    const int g = lane >> 2, t = lane & 3;
    const int by8  = blockIdx.y * 8;       // first m-tile16 of block
    const int bnt0 = blockIdx.x * 2;       // first n-tile64 of block
    const int mtb  = (warp >> 1) * 4;      // warp's first local m-tile
    const int ntl  = warp & 1;             // warp's local n-tile

    float c[4][8][4];
    #pragma unroll
    for (int mt = 0; mt < 4; mt++)
        #pragma unroll
        for (int nt = 0; nt < 8; nt++)
            #pragma unroll
            for (int i = 0; i < 4; i++) c[mt][nt][i] = 0.0f;

    auto load_tile = [&](int stg, int kt) {
        const uint32_t sb = sbase + stg * (STG_WORDS * 4);
        #pragma unroll
        for (int i = 0; i < 4; i++) {
            int ca = tid + i * 128;                 // 0..511 (A chunks)
            int amt = ca >> 6, as = (ca >> 5) & 1, al2 = ca & 31;
            size_t goA = ((size_t)((by8 + amt) * 64 + kt * 2 + as)) * 128 + al2 * 4;
            uint32_t soA = ((amt * 2 + as) * 128 + al2 * 4) * 4;
            cpasync16(sb + soA,              Ah + goA);
            cpasync16(sb + 2048 * 4 + soA,   Al + goA);
            int bnt = ca >> 8, bs = (ca >> 7) & 1, lq = ca & 127;
            size_t goB = ((size_t)((bnt0 + bnt) * 64 + kt * 2 + bs)) * 512 + lq * 4;
            uint32_t soB = ((bnt * 2 + bs) * 512 + lq * 4) * 4;
            cpasync16(sb + 4096 * 4 + soB,   Bh + goB);
            cpasync16(sb + 6144 * 4 + soB,   Bl + goB);
        }
        asm volatile("cp.async.commit_group;" ::: "memory");
    };

    const int NKI = K / 32;
    load_tile(0, 0);

    #pragma unroll 1
    for (int kt = 0; kt < NKI; kt++) {
        if (kt + 1 < NKI) {
            load_tile((kt + 1) & 1, kt + 1);
            asm volatile("cp.async.wait_group 1;" ::: "memory");
        } else {
            asm volatile("cp.async.wait_group 0;" ::: "memory");
        }
        __syncthreads();

        const uint32_t* St = smw + (kt & 1) * STG_WORDS;

        #pragma unroll
        for (int s = 0; s < 2; s++) {
            uint4 ah[4], al[4];
            #pragma unroll
            for (int mt = 0; mt < 4; mt++) {
                int mo = ((mtb + mt) * 2 + s) * 128 + lane * 4;
                ah[mt] = *(const uint4*)(St + mo);
                al[mt] = *(const uint4*)(St + 2048 + mo);
            }
            uint32_t bh[16], bl[16];
            {
                int bo = (ntl * 2 + s) * 512 + lane * 16;
                #pragma unroll
                for (int q = 0; q < 4; q++) {
                    uint4 vh = *(const uint4*)(St + 4096 + bo + q * 4);
                    uint4 vl = *(const uint4*)(St + 6144 + bo + q * 4);
                    bh[q*4] = vh.x; bh[q*4+1] = vh.y; bh[q*4+2] = vh.z; bh[q*4+3] = vh.w;
                    bl[q*4] = vl.x; bl[q*4+1] = vl.y; bl[q*4+2] = vl.z; bl[q*4+3] = vl.w;
                }
            }
            #pragma unroll
            for (int mt = 0; mt < 4; mt++)
                #pragma unroll
                for (int nt = 0; nt < 8; nt++) {
                    mma_bf16(c[mt][nt], ah[mt].x, ah[mt].y, ah[mt].z, ah[mt].w,
                             bh[nt], bh[8 + nt]);
                    mma_bf16(c[mt][nt], ah[mt].x, ah[mt].y, ah[mt].z, ah[mt].w,
                             bl[nt], bl[8 + nt]);
                    mma_bf16(c[mt][nt], al[mt].x, al[mt].y, al[mt].z, al[mt].w,
                             bh[nt], bh[8 + nt]);
                }
        }
        __syncthreads();
    }

    #pragma unroll
    for (int mt = 0; mt < 4; mt++)
        #pragma unroll
        for (int nt = 0; nt < 8; nt++) {
            int m = by8 * 16 + (mtb + mt) * 16 + g;
            int n = bnt0 * 64 + ntl * 64 + nt * 8 + t * 2;
            float2 v0 = make_float2(c[mt][nt][0], c[mt][nt][1]);
            float2 v1 = make_float2(c[mt][nt][2], c[mt][nt][3]);
            if (round_out) {
                v0.x = f2tf(v0.x); v0.y = f2tf(v0.y);
                v1.x = f2tf(v1.x); v1.y = f2tf(v1.y);
            }
            *(float2*)(C + (size_t)m * N + n)       = v0;
            *(float2*)(C + (size_t)(m + 8) * N + n) = v1;
        }
}

// ---------------------------------------------------------------------------
// Tensor-core causal flash attention v3: as R10 but K/V tiles via 2-stage
// cp.async double buffer and NO converts on load (Q/K/V pre-rounded to tf32
// by the GEMM epilogue).
// Stage (words): Ks[64][68] then Vs[64][72]; Ps after both stages.
// ---------------------------------------------------------------------------
#define KSS 68
#define VSS 72
#define PSS 68
#define SKV (64 * KSS + 64 * VSS)                       // 8960 words/stage
#define ATTN_SMEM ((2 * SKV + 128 * PSS) * 4)           // 106496 bytes

__global__ __launch_bounds__(128) void attn_mma2(
    const float* __restrict__ Q, const float* __restrict__ K,
    const float* __restrict__ V, float* __restrict__ O)
{
    extern __shared__ float smem[];
    const uint32_t sbase = (uint32_t)__cvta_generic_to_shared(smem);
    float* Ps = smem + 2 * SKV;

    const int tid  = threadIdx.x;
    const int lane = tid & 31, warp = tid >> 5;
    const int g = lane >> 2, t = lane & 3;
    const int h = blockIdx.y, b = blockIdx.z;
    const size_t tok0 = (size_t)b * SEQ;
    float* Pw = Ps + warp * 32 * PSS;

    auto load_kv = [&](int stg, int kt) {
        const uint32_t sb = sbase + stg * (SKV * 4);
        #pragma unroll
        for (int i = 0; i < 8; i++) {
            int c = tid + i * 128;                  // 0..1023
            int r = c >> 4, c4 = (c & 15) << 2;
            const size_t base = (tok0 + kt * 64 + r) * DMODEL + h * HD + c4;
            cpasync16(sb + (r * KSS + c4) * 4,             K + base);
            cpasync16(sb + (64 * KSS + r * VSS + c4) * 4,  V + base);
        }
        asm volatile("cp.async.commit_group;" ::: "memory");
    };

    #pragma unroll 1
    for (int pass = 0; pass < 2; pass++) {
        const int qt = pass ? (15 - (int)blockIdx.x) : (int)blockIdx.x;
        const int r0 = qt * 128 + warp * 32;

        __syncthreads();           // all warps done with previous pass smem
        load_kv(0, 0);

        // Q fragments (already tf32; *0.125 is exact)
        uint32_t qf[2][8][4];
        #pragma unroll
        for (int mi = 0; mi < 2; mi++) {
            const float* qa = Q + (tok0 + r0 + mi * 16 + g) * DMODEL + h * HD;
            const float* qb = qa + 8 * DMODEL;
            #pragma unroll
            for (int kc = 0; kc < 8; kc++) {
                qf[mi][kc][0] = __float_as_uint(qa[kc * 8 + t] * 0.125f);
                qf[mi][kc][1] = __float_as_uint(qb[kc * 8 + t] * 0.125f);
                qf[mi][kc][2] = __float_as_uint(qa[kc * 8 + t + 4] * 0.125f);
                qf[mi][kc][3] = __float_as_uint(qb[kc * 8 + t + 4] * 0.125f);
            }
        }

        float o[2][8][4];
        #pragma unroll
        for (int mi = 0; mi < 2; mi++)
            #pragma unroll
            for (int nt = 0; nt < 8; nt++)
                #pragma unroll
                for (int i = 0; i < 4; i++) o[mi][nt][i] = 0.0f;
        float mx[2][2] = {{-INFINITY, -INFINITY}, {-INFINITY, -INFINITY}};
        float ll[2][2] = {{0.0f, 0.0f}, {0.0f, 0.0f}};

        const int ktmax = 2 * qt + 1;
        #pragma unroll 1
        for (int kt = 0; kt <= ktmax; kt++) {
            asm volatile("cp.async.wait_group 0;" ::: "memory");
            __syncthreads();                 // stage kt ready; prev compute done
            if (kt + 1 <= ktmax) load_kv((kt + 1) & 1, kt + 1);

            if (kt * 64 > r0 + 31) continue;   // fully masked for this warp
            const bool diag = (kt >= 2 * qt);

            const float* Ks = smem + (kt & 1) * SKV;
            const float* Vs = Ks + 64 * KSS;

            #pragma unroll 1
            for (int ch = 0; ch < 2; ch++) {
                float sc[2][4][4];
                #pragma unroll
                for (int mi = 0; mi < 2; mi++)
                    #pragma unroll
                    for (int nt = 0; nt < 4; nt++)
                        #pragma unroll
                        for (int i = 0; i < 4; i++) sc[mi][nt][i] = 0.0f;
                #pragma unroll
                for (int nt = 0; nt < 4; nt++) {
                    const float* kb = Ks + (ch * 32 + nt * 8 + g) * KSS;
                    #pragma unroll
                    for (int kc = 0; kc < 8; kc++) {
                        uint32_t b0 = __float_as_uint(kb[kc * 8 + t]);
                        uint32_t b1 = __float_as_uint(kb[kc * 8 + t + 4]);
                        mma_tf32(sc[0][nt], qf[0][kc][0], qf[0][kc][1],
                                 qf[0][kc][2], qf[0][kc][3], b0, b1);
                        mma_tf32(sc[1][nt], qf[1][kc][0], qf[1][kc][1],
                                 qf[1][kc][2], qf[1][kc][3], b0, b1);
                    }
                }

                if (diag) {
                    #pragma unroll
                    for (int mi = 0; mi < 2; mi++) {
                        const int ra = r0 + mi * 16 + g, rb = ra + 8;
                        #pragma unroll
                        for (int nt = 0; nt < 4; nt++) {
                            int c0 = kt * 64 + ch * 32 + nt * 8 + 2 * t;
                            int c1 = c0 + 1;
                            if (c0 > ra) sc[mi][nt][0] = -INFINITY;
                            if (c1 > ra) sc[mi][nt][1] = -INFINITY;
                            if (c0 > rb) sc[mi][nt][2] = -INFINITY;
                            if (c1 > rb) sc[mi][nt][3] = -INFINITY;
                        }
                    }
                }

                #pragma unroll
                for (int mi = 0; mi < 2; mi++) {
                    float tm0 = -INFINITY, tm1 = -INFINITY;
                    #pragma unroll
                    for (int nt = 0; nt < 4; nt++) {
                        tm0 = fmaxf(tm0, fmaxf(sc[mi][nt][0], sc[mi][nt][1]));
                        tm1 = fmaxf(tm1, fmaxf(sc[mi][nt][2], sc[mi][nt][3]));
                    }
                    tm0 = fmaxf(tm0, __shfl_xor_sync(0xffffffffu, tm0, 1));
                    tm0 = fmaxf(tm0, __shfl_xor_sync(0xffffffffu, tm0, 2));
                    tm1 = fmaxf(tm1, __shfl_xor_sync(0xffffffffu, tm1, 1));
                    tm1 = fmaxf(tm1, __shfl_xor_sync(0xffffffffu, tm1, 2));

                    const float m0n = fmaxf(mx[mi][0], tm0);
                    const float m1n = fmaxf(mx[mi][1], tm1);
                    const float cs0 = __expf(mx[mi][0] - m0n);
                    const float cs1 = __expf(mx[mi][1] - m1n);
                    ll[mi][0] *= cs0; ll[mi][1] *= cs1;
                    #pragma unroll
                    for (int nt = 0; nt < 8; nt++) {
                        o[mi][nt][0] *= cs0; o[mi][nt][1] *= cs0;
                        o[mi][nt][2] *= cs1; o[mi][nt][3] *= cs1;
                    }
                    mx[mi][0] = m0n; mx[mi][1] = m1n;

                    float* pr0 = Pw + (mi * 16 + g) * PSS + ch * 32;
                    float* pr1 = pr0 + 8 * PSS;
                    #pragma unroll
                    for (int nt = 0; nt < 4; nt++) {
                        float p0 = __expf(sc[mi][nt][0] - m0n);
                        float p1 = __expf(sc[mi][nt][1] - m0n);
                        float p2 = __expf(sc[mi][nt][2] - m1n);
                        float p3 = __expf(sc[mi][nt][3] - m1n);
                        ll[mi][0] += p0 + p1; ll[mi][1] += p2 + p3;
                        *(float2*)(pr0 + nt * 8 + 2 * t) = make_float2(f2tf(p0), f2tf(p1));
                        *(float2*)(pr1 + nt * 8 + 2 * t) = make_float2(f2tf(p2), f2tf(p3));
                    }
                }
                __syncwarp();

                #pragma unroll
                for (int kc = 0; kc < 4; kc++) {
                    const int kr = ch * 32 + kc * 8;
                    uint32_t a[2][4];
                    #pragma unroll
                    for (int mi = 0; mi < 2; mi++) {
                        const float* p0 = Pw + (mi * 16 + g) * PSS + kr + t;
                        const float* p1 = p0 + 8 * PSS;
                        a[mi][0] = __float_as_uint(p0[0]);
                        a[mi][1] = __float_as_uint(p1[0]);
                        a[mi][2] = __float_as_uint(p0[4]);
                        a[mi][3] = __float_as_uint(p1[4]);
                    }
                    const float* vb0 = Vs + (kr + t) * VSS + g;
                    const float* vb1 = Vs + (kr + t + 4) * VSS + g;
                    #pragma unroll
                    for (int nt = 0; nt < 8; nt++) {
                        uint32_t b0 = __float_as_uint(vb0[nt * 8]);
                        uint32_t b1 = __float_as_uint(vb1[nt * 8]);
                        mma_tf32(o[0][nt], a[0][0], a[0][1], a[0][2], a[0][3], b0, b1);
                        mma_tf32(o[1][nt], a[1][0], a[1][1], a[1][2], a[1][3], b0, b1);
                    }
                }
                __syncwarp();
            } // ch
        } // kt

        #pragma unroll
        for (int mi = 0; mi < 2; mi++) {
            float l0 = ll[mi][0], l1 = ll[mi][1];
            l0 += __shfl_xor_sync(0xffffffffu, l0, 1);
            l0 += __shfl_xor_sync(0xffffffffu, l0, 2);
            l1 += __shfl_xor_sync(0xffffffffu, l1, 1);
            l1 += __shfl_xor_sync(0xffffffffu, l1, 2);
            const float i0 = 1.0f / l0, i1 = 1.0f / l1;

            float* oa = O + (tok0 + r0 + mi * 16 + g) * DMODEL + h * HD;
            float* ob = oa + 8 * DMODEL;
            #pragma unroll
            for (int nt = 0; nt < 8; nt++) {
                *(float2*)(oa + nt * 8 + 2 * t) =
                    make_float2(o[mi][nt][0] * i0, o[mi][nt][1] * i0);
                *(float2*)(ob + nt * 8 + 2 * t) =
                    make_float2(o[mi][nt][2] * i1, o[mi][nt][3] * i1);
            }
        }
    } // pass
}

// ---------------------------------------------------------------------------
// Launch
// ---------------------------------------------------------------------------
extern "C" void kernel_launch(void* const* d_in, const int* in_sizes, int n_in,
                              void* d_out, int out_size)
{
    const float* x   = (const float*)d_in[0];
    const float* W_q = (const float*)d_in[1];
    const float* W_k = (const float*)d_in[2];
    const float* W_v = (const float*)d_in[3];
    const float* W_o = (const float*)d_in[4];
    float* out = (float*)d_out;

    float *Qp, *Kp, *Vp, *Ap;
    cudaGetSymbolAddress((void**)&Qp, g_Q);
    cudaGetSymbolAddress((void**)&Kp, g_K);
    cudaGetSymbolAddress((void**)&Vp, g_V);
    cudaGetSymbolAddress((void**)&Ap, g_A);

    uint32_t *xh, *xl, *ah, *al;
    uint32_t *wqh, *wql, *wkh, *wkl, *wvh, *wvl, *woh, *wol;
    cudaGetSymbolAddress((void**)&xh,  g_xh);  cudaGetSymbolAddress((void**)&xl,  g_xl);
    cudaGetSymbolAddress((void**)&ah,  g_ah);  cudaGetSymbolAddress((void**)&al,  g_al);
    cudaGetSymbolAddress((void**)&wqh, g_wqh); cudaGetSymbolAddress((void**)&wql, g_wql);
    cudaGetSymbolAddress((void**)&wkh, g_wkh); cudaGetSymbolAddress((void**)&wkl, g_wkl);
    cudaGetSymbolAddress((void**)&wvh, g_wvh); cudaGetSymbolAddress((void**)&wvl, g_wvl);
    cudaGetSymbolAddress((void**)&woh, g_woh); cudaGetSymbolAddress((void**)&wol, g_wol);

    cudaFuncSetAttribute(gemm_bf16p, cudaFuncAttributeMaxDynamicSharedMemorySize, GEMM_SMEM);
    cudaFuncSetAttribute(attn_mma2, cudaFuncAttributeMaxDynamicSharedMemorySize, ATTN_SMEM);

    const int xthr = (NT / 16) * 64 * 32;     // 524288 (A'-layout threads)
    const int wthr = 16 * 64 * 32;            // 32768  (B'-layout threads/weight)

    split_rowsF<<<(xthr + 255) / 256, 256>>>(x, xh, xl, xthr);
    dim3 wgrd((wthr + 255) / 256, 4);
    split_cols4F<<<wgrd, 256>>>(W_q, W_k, W_v, W_o,
                                wqh, wql, wkh, wkl, wvh, wvl, woh, wol, wthr);

    dim3 ggrd(DMODEL / 128, NT / 128);   // (8, 32)

    gemm_bf16p<<<ggrd, 128, GEMM_SMEM>>>(xh, xl, wqh, wql, Qp, NT, DMODEL, DMODEL, 1);
    gemm_bf16p<<<ggrd, 128, GEMM_SMEM>>>(xh, xl, wkh, wkl, Kp, NT, DMODEL, DMODEL, 1);
    gemm_bf16p<<<ggrd, 128, GEMM_SMEM>>>(xh, xl, wvh, wvl, Vp, NT, DMODEL, DMODEL, 1);

    dim3 agrd(8, NHEAD, BATCH);
    attn_mma2<<<agrd, 128, ATTN_SMEM>>>(Qp, Kp, Vp, Ap);

    split_rowsF<<<(xthr + 255) / 256, 256>>>(Ap, ah, al, xthr);
    gemm_bf16p<<<ggrd, 128, GEMM_SMEM>>>(ah, al, woh, wol, out, NT, DMODEL, DMODEL, 0);
}

// round 17
// speedup vs baseline: 1.0558x; 1.0558x over previous
#include <cuda_runtime.h>
#include <cuda_bf16.h>
#include <math.h>
#include <stdint.h>

// Problem constants
#define NT     4096        // B*S tokens
#define DMODEL 1024
#define NHEAD  16
#define HD     64
#define SEQ    2048
#define BATCH  2
#define KWRD   (DMODEL / 2)   // 512 bf16x2 words per row

// Scratch (no cudaMalloc allowed)
__device__ float g_Q[(size_t)NT * DMODEL];
__device__ float g_K[(size_t)NT * DMODEL];
__device__ float g_V[(size_t)NT * DMODEL];
__device__ float g_A[(size_t)NT * DMODEL];

// Pre-split bf16 hi/lo buffers (packed bf16x2 words)
__device__ uint32_t g_xh[(size_t)NT * KWRD],  g_xl[(size_t)NT * KWRD];
__device__ uint32_t g_ah[(size_t)NT * KWRD],  g_al[(size_t)NT * KWRD];
__device__ uint32_t g_wqh[(size_t)KWRD * DMODEL], g_wql[(size_t)KWRD * DMODEL];
__device__ uint32_t g_wkh[(size_t)KWRD * DMODEL], g_wkl[(size_t)KWRD * DMODEL];
__device__ uint32_t g_wvh[(size_t)KWRD * DMODEL], g_wvl[(size_t)KWRD * DMODEL];
__device__ uint32_t g_woh[(size_t)KWRD * DMODEL], g_wol[(size_t)KWRD * DMODEL];

__device__ __forceinline__ float f2tf(float x) {
    uint32_t r; asm("cvt.rna.tf32.f32 %0, %1;" : "=r"(r) : "f"(x));
    return __uint_as_float(r);
}

__device__ __forceinline__ void mma_tf32(float c[4], uint32_t a0, uint32_t a1,
                                         uint32_t a2, uint32_t a3,
                                         uint32_t b0, uint32_t b1) {
    asm volatile(
        "mma.sync.aligned.m16n8k8.row.col.f32.tf32.tf32.f32 "
        "{%0,%1,%2,%3}, {%4,%5,%6,%7}, {%8,%9}, {%0,%1,%2,%3};\n"
        : "+f"(c[0]), "+f"(c[1]), "+f"(c[2]), "+f"(c[3])
        : "r"(a0), "r"(a1), "r"(a2), "r"(a3), "r"(b0), "r"(b1));
}

__device__ __forceinline__ void mma_bf16(float c[4], uint32_t a0, uint32_t a1,
                                         uint32_t a2, uint32_t a3,
                                         uint32_t b0, uint32_t b1) {
    asm volatile(
        "mma.sync.aligned.m16n8k16.row.col.f32.bf16.bf16.f32 "
        "{%0,%1,%2,%3}, {%4,%5,%6,%7}, {%8,%9}, {%0,%1,%2,%3};\n"
        : "+f"(c[0]), "+f"(c[1]), "+f"(c[2]), "+f"(c[3])
        : "r"(a0), "r"(a1), "r"(a2), "r"(a3), "r"(b0), "r"(b1));
}

__device__ __forceinline__ uint32_t split_pack(float x, float y, uint32_t& lo_w) {
    __nv_bfloat16 hx = __float2bfloat16(x);
    __nv_bfloat16 hy = __float2bfloat16(y);
    __nv_bfloat16 lx = __float2bfloat16(x - __bfloat162float(hx));
    __nv_bfloat16 ly = __float2bfloat16(y - __bfloat162float(hy));
    lo_w = ((uint32_t)__bfloat16_as_ushort(ly) << 16) | __bfloat16_as_ushort(lx);
    return ((uint32_t)__bfloat16_as_ushort(hy) << 16) | __bfloat16_as_ushort(hx);
}

__device__ __forceinline__ void cpasync16(uint32_t s, const void* g) {
    asm volatile("cp.async.cg.shared.global [%0], [%1], 16;"
                 :: "r"(s), "l"(g) : "memory");
}

// ---------------------------------------------------------------------------
// Split kernels (R12/R13 layouts: A [M][K/2] words row-major; B [K/2][N]).
// ---------------------------------------------------------------------------
__global__ void split_rows(const float* __restrict__ X, uint32_t* __restrict__ H,
                           uint32_t* __restrict__ L, int nwords)
{
    int i = blockIdx.x * blockDim.x + threadIdx.x;
    if (i < nwords) {
        float2 v = *(const float2*)(X + 2 * (size_t)i);
        uint32_t lo; uint32_t hi = split_pack(v.x, v.y, lo);
        H[i] = hi; L[i] = lo;
    }
}

__global__ void split_cols4(
    const float* __restrict__ W0, const float* __restrict__ W1,
    const float* __restrict__ W2, const float* __restrict__ W3,
    uint32_t* __restrict__ H0, uint32_t* __restrict__ L0,
    uint32_t* __restrict__ H1, uint32_t* __restrict__ L1,
    uint32_t* __restrict__ H2, uint32_t* __restrict__ L2,
    uint32_t* __restrict__ H3, uint32_t* __restrict__ L3,
    int N, int nwords)
{
    const int wsel = blockIdx.y;
    const float* W = (wsel == 0) ? W0 : (wsel == 1) ? W1 : (wsel == 2) ? W2 : W3;
    uint32_t* H = (wsel == 0) ? H0 : (wsel == 1) ? H1 : (wsel == 2) ? H2 : H3;
    uint32_t* L = (wsel == 0) ? L0 : (wsel == 1) ? L1 : (wsel == 2) ? L2 : L3;
    int i = blockIdx.x * blockDim.x + threadIdx.x;
    if (i < nwords) {
        int kk = i / N, n = i - kk * N;
        float a = W[(size_t)(2 * kk) * N + n];
        float b = W[(size_t)(2 * kk + 1) * N + n];
        uint32_t lo; uint32_t hi = split_pack(a, b, lo);
        H[i] = hi; L[i] = lo;
    }
}

// ---------------------------------------------------------------------------
// 3xBF16 GEMM (R13-proven config) with multi-output select via blockIdx.z.
// 128 threads (4 warps), block tile 128x128, warp tile 64x64, BK=32,
// 2-stage cp.async double buffer.
// Smem: A [m][kw] stride AW=20 (frag banks 20g+t conflict-free),
//       B [kw][n] stride BW=132 (frag banks 4t+g conflict-free).
// ---------------------------------------------------------------------------
#define AW 20
#define BW 132
#define AS_WORDS (128 * AW)                      // 2560
#define BS_WORDS (16 * BW)                       // 2112
#define STG_WORDS (2 * AS_WORDS + 2 * BS_WORDS)  // 9344
#define GEMM_SMEM (2 * STG_WORDS * 4)            // 74752 bytes

__global__ __launch_bounds__(128) void gemm_bf16p(
    const uint32_t* __restrict__ Ah, const uint32_t* __restrict__ Al,
    const uint32_t* __restrict__ B0h, const uint32_t* __restrict__ B0l,
    float* __restrict__ C0,
    const uint32_t* __restrict__ B1h, const uint32_t* __restrict__ B1l,
    float* __restrict__ C1,
    const uint32_t* __restrict__ B2h, const uint32_t* __restrict__ B2l,
    float* __restrict__ C2,
    int N, int K, int round_out)
{
    extern __shared__ uint32_t smw[];
    const uint32_t sbase = (uint32_t)__cvta_generic_to_shared(smw);

    const int wsel = blockIdx.z;
    const uint32_t* Bh = (wsel == 0) ? B0h : (wsel == 1) ? B1h : B2h;
    const uint32_t* Bl = (wsel == 0) ? B0l : (wsel == 1) ? B1l : B2l;
    float* C = (wsel == 0) ? C0 : (wsel == 1) ? C1 : C2;

    const int KW = K >> 1;
    const int tid  = threadIdx.x;
    const int lane = tid & 31;
    const int warp = tid >> 5;
    const int g = lane >> 2, t = lane & 3;
    const int wm = (warp >> 1) * 64;
    const int wn = (warp & 1) * 64;
    const int m0 = blockIdx.y * 128;
    const int n0 = blockIdx.x * 128;

    float c[4][8][4];
    #pragma unroll
    for (int mt = 0; mt < 4; mt++)
        #pragma unroll
        for (int nt = 0; nt < 8; nt++)
            #pragma unroll
            for (int i = 0; i < 4; i++) c[mt][nt][i] = 0.0f;

    auto load_tile = [&](int stg, int ktw) {
        const uint32_t sb = sbase + stg * (STG_WORDS * 4);
        #pragma unroll
        for (int i = 0; i < 4; i++) {
            int idx = tid + i * 128;                    // 0..511
            int am = idx >> 2, aq = (idx & 3) << 2;     // A: 128 rows x 4 uint4
            cpasync16(sb + (am * AW + aq) * 4,
                      Ah + (size_t)(m0 + am) * KW + ktw + aq);
            cpasync16(sb + (AS_WORDS + am * AW + aq) * 4,
                      Al + (size_t)(m0 + am) * KW + ktw + aq);
            int bk = idx >> 5, bn = (idx & 31) << 2;    // B: 16 wrows x 32 uint4
            cpasync16(sb + (2 * AS_WORDS + bk * BW + bn) * 4,
                      Bh + (size_t)(ktw + bk) * N + n0 + bn);
            cpasync16(sb + (2 * AS_WORDS + BS_WORDS + bk * BW + bn) * 4,
                      Bl + (size_t)(ktw + bk) * N + n0 + bn);
        }
        asm volatile("cp.async.commit_group;" ::: "memory");
    };

    const int NKI = K / 32;
    load_tile(0, 0);

    #pragma unroll 1
    for (int kt = 0; kt < NKI; kt++) {
        if (kt + 1 < NKI) {
            load_tile((kt + 1) & 1, (kt + 1) * 16);
            asm volatile("cp.async.wait_group 1;" ::: "memory");
        } else {
            asm volatile("cp.async.wait_group 0;" ::: "memory");
        }
        __syncthreads();

        const uint32_t* As_h = smw + (kt & 1) * STG_WORDS;
        const uint32_t* As_l = As_h + AS_WORDS;
        const uint32_t* Bs_h = As_h + 2 * AS_WORDS;
        const uint32_t* Bs_l = Bs_h + BS_WORDS;

        #pragma unroll
        for (int s = 0; s < 2; s++) {
            uint32_t ah[4][4], al[4][4];
            #pragma unroll
            for (int mt = 0; mt < 4; mt++) {
                int m = wm + mt * 16 + g;
                const uint32_t* ph = As_h + m * AW + s * 8 + t;
                const uint32_t* pl = As_l + m * AW + s * 8 + t;
                ah[mt][0] = ph[0];
                ah[mt][1] = ph[8 * AW];
                ah[mt][2] = ph[4];
                ah[mt][3] = ph[8 * AW + 4];
                al[mt][0] = pl[0];
                al[mt][1] = pl[8 * AW];
                al[mt][2] = pl[4];
                al[mt][3] = pl[8 * AW + 4];
            }
            uint32_t bh[8][2], bl[8][2];
            #pragma unroll
            for (int nt = 0; nt < 8; nt++) {
                int n = wn + nt * 8 + g;
                bh[nt][0] = Bs_h[(s * 8 + t) * BW + n];
                bh[nt][1] = Bs_h[(s * 8 + 4 + t) * BW + n];
                bl[nt][0] = Bs_l[(s * 8 + t) * BW + n];
                bl[nt][1] = Bs_l[(s * 8 + 4 + t) * BW + n];
            }
            #pragma unroll
            for (int mt = 0; mt < 4; mt++)
                #pragma unroll
                for (int nt = 0; nt < 8; nt++) {
                    mma_bf16(c[mt][nt], ah[mt][0], ah[mt][1], ah[mt][2], ah[mt][3],
                             bh[nt][0], bh[nt][1]);
                    mma_bf16(c[mt][nt], ah[mt][0], ah[mt][1], ah[mt][2], ah[mt][3],
                             bl[nt][0], bl[nt][1]);
                    mma_bf16(c[mt][nt], al[mt][0], al[mt][1], al[mt][2], al[mt][3],
                             bh[nt][0], bh[nt][1]);
                }
        }
        __syncthreads();
    }

    #pragma unroll
    for (int mt = 0; mt < 4; mt++)
        #pragma unroll
        for (int nt = 0; nt < 8; nt++) {
            int m = m0 + wm + mt * 16 + g;
            int n = n0 + wn + nt * 8 + t * 2;
            float2 v0 = make_float2(c[mt][nt][0], c[mt][nt][1]);
            float2 v1 = make_float2(c[mt][nt][2], c[mt][nt][3]);
            if (round_out) {
                v0.x = f2tf(v0.x); v0.y = f2tf(v0.y);
                v1.x = f2tf(v1.x); v1.y = f2tf(v1.y);
            }
            *(float2*)(C + (size_t)m * N + n)       = v0;
            *(float2*)(C + (size_t)(m + 8) * N + n) = v1;
        }
}

// ---------------------------------------------------------------------------
// Tensor-core causal flash attention v3 (R14-proven): cp.async double-buffered
// K/V, no converts (Q/K/V pre-rounded to tf32 by GEMM epilogue).
// ---------------------------------------------------------------------------
#define KSS 68
#define VSS 72
#define PSS 68
#define SKV (64 * KSS + 64 * VSS)
#define ATTN_SMEM ((2 * SKV + 128 * PSS) * 4)   // 106496 bytes

__global__ __launch_bounds__(128) void attn_mma2(
    const float* __restrict__ Q, const float* __restrict__ K,
    const float* __restrict__ V, float* __restrict__ O)
{
    extern __shared__ float smem[];
    const uint32_t sbase = (uint32_t)__cvta_generic_to_shared(smem);
    float* Ps = smem + 2 * SKV;

    const int tid  = threadIdx.x;
    const int lane = tid & 31, warp = tid >> 5;
    const int g = lane >> 2, t = lane & 3;
    const int h = blockIdx.y, b = blockIdx.z;
    const size_t tok0 = (size_t)b * SEQ;
    float* Pw = Ps + warp * 32 * PSS;

    auto load_kv = [&](int stg, int kt) {
        const uint32_t sb = sbase + stg * (SKV * 4);
        #pragma unroll
        for (int i = 0; i < 8; i++) {
            int c = tid + i * 128;
            int r = c >> 4, c4 = (c & 15) << 2;
            const size_t base = (tok0 + kt * 64 + r) * DMODEL + h * HD + c4;
            cpasync16(sb + (r * KSS + c4) * 4,             K + base);
            cpasync16(sb + (64 * KSS + r * VSS + c4) * 4,  V + base);
        }
        asm volatile("cp.async.commit_group;" ::: "memory");
    };

    #pragma unroll 1
    for (int pass = 0; pass < 2; pass++) {
        const int qt = pass ? (15 - (int)blockIdx.x) : (int)blockIdx.x;
        const int r0 = qt * 128 + warp * 32;

        __syncthreads();
        load_kv(0, 0);

        uint32_t qf[2][8][4];
        #pragma unroll
        for (int mi = 0; mi < 2; mi++) {
            const float* qa = Q + (tok0 + r0 + mi * 16 + g) * DMODEL + h * HD;
            const float* qb = qa + 8 * DMODEL;
            #pragma unroll
            for (int kc = 0; kc < 8; kc++) {
                qf[mi][kc][0] = __float_as_uint(qa[kc * 8 + t] * 0.125f);
                qf[mi][kc][1] = __float_as_uint(qb[kc * 8 + t] * 0.125f);
                qf[mi][kc][2] = __float_as_uint(qa[kc * 8 + t + 4] * 0.125f);
                qf[mi][kc][3] = __float_as_uint(qb[kc * 8 + t + 4] * 0.125f);
            }
        }

        float o[2][8][4];
        #pragma unroll
        for (int mi = 0; mi < 2; mi++)
            #pragma unroll
            for (int nt = 0; nt < 8; nt++)
                #pragma unroll
                for (int i = 0; i < 4; i++) o[mi][nt][i] = 0.0f;
        float mx[2][2] = {{-INFINITY, -INFINITY}, {-INFINITY, -INFINITY}};
        float ll[2][2] = {{0.0f, 0.0f}, {0.0f, 0.0f}};

        const int ktmax = 2 * qt + 1;
        #pragma unroll 1
        for (int kt = 0; kt <= ktmax; kt++) {
            asm volatile("cp.async.wait_group 0;" ::: "memory");
            __syncthreads();
            if (kt + 1 <= ktmax) load_kv((kt + 1) & 1, kt + 1);

            if (kt * 64 > r0 + 31) continue;
            const bool diag = (kt >= 2 * qt);

            const float* Ks = smem + (kt & 1) * SKV;
            const float* Vs = Ks + 64 * KSS;

            #pragma unroll 1
            for (int ch = 0; ch < 2; ch++) {
                float sc[2][4][4];
                #pragma unroll
                for (int mi = 0; mi < 2; mi++)
                    #pragma unroll
                    for (int nt = 0; nt < 4; nt++)
                        #pragma unroll
                        for (int i = 0; i < 4; i++) sc[mi][nt][i] = 0.0f;
                #pragma unroll
                for (int nt = 0; nt < 4; nt++) {
                    const float* kb = Ks + (ch * 32 + nt * 8 + g) * KSS;
                    #pragma unroll
                    for (int kc = 0; kc < 8; kc++) {
                        uint32_t b0 = __float_as_uint(kb[kc * 8 + t]);
                        uint32_t b1 = __float_as_uint(kb[kc * 8 + t + 4]);
                        mma_tf32(sc[0][nt], qf[0][kc][0], qf[0][kc][1],
                                 qf[0][kc][2], qf[0][kc][3], b0, b1);
                        mma_tf32(sc[1][nt], qf[1][kc][0], qf[1][kc][1],
                                 qf[1][kc][2], qf[1][kc][3], b0, b1);
                    }
                }

                if (diag) {
                    #pragma unroll
                    for (int mi = 0; mi < 2; mi++) {
                        const int ra = r0 + mi * 16 + g, rb = ra + 8;
                        #pragma unroll
                        for (int nt = 0; nt < 4; nt++) {
                            int c0 = kt * 64 + ch * 32 + nt * 8 + 2 * t;
                            int c1 = c0 + 1;
                            if (c0 > ra) sc[mi][nt][0] = -INFINITY;
                            if (c1 > ra) sc[mi][nt][1] = -INFINITY;
                            if (c0 > rb) sc[mi][nt][2] = -INFINITY;
                            if (c1 > rb) sc[mi][nt][3] = -INFINITY;
                        }
                    }
                }

                #pragma unroll
                for (int mi = 0; mi < 2; mi++) {
                    float tm0 = -INFINITY, tm1 = -INFINITY;
                    #pragma unroll
                    for (int nt = 0; nt < 4; nt++) {
                        tm0 = fmaxf(tm0, fmaxf(sc[mi][nt][0], sc[mi][nt][1]));
                        tm1 = fmaxf(tm1, fmaxf(sc[mi][nt][2], sc[mi][nt][3]));
                    }
                    tm0 = fmaxf(tm0, __shfl_xor_sync(0xffffffffu, tm0, 1));
                    tm0 = fmaxf(tm0, __shfl_xor_sync(0xffffffffu, tm0, 2));
                    tm1 = fmaxf(tm1, __shfl_xor_sync(0xffffffffu, tm1, 1));
                    tm1 = fmaxf(tm1, __shfl_xor_sync(0xffffffffu, tm1, 2));

                    const float m0n = fmaxf(mx[mi][0], tm0);
                    const float m1n = fmaxf(mx[mi][1], tm1);
                    const float cs0 = __expf(mx[mi][0] - m0n);
                    const float cs1 = __expf(mx[mi][1] - m1n);
                    ll[mi][0] *= cs0; ll[mi][1] *= cs1;
                    #pragma unroll
                    for (int nt = 0; nt < 8; nt++) {
                        o[mi][nt][0] *= cs0; o[mi][nt][1] *= cs0;
                        o[mi][nt][2] *= cs1; o[mi][nt][3] *= cs1;
                    }
                    mx[mi][0] = m0n; mx[mi][1] = m1n;

                    float* pr0 = Pw + (mi * 16 + g) * PSS + ch * 32;
                    float* pr1 = pr0 + 8 * PSS;
                    #pragma unroll
                    for (int nt = 0; nt < 4; nt++) {
                        float p0 = __expf(sc[mi][nt][0] - m0n);
                        float p1 = __expf(sc[mi][nt][1] - m0n);
                        float p2 = __expf(sc[mi][nt][2] - m1n);
                        float p3 = __expf(sc[mi][nt][3] - m1n);
                        ll[mi][0] += p0 + p1; ll[mi][1] += p2 + p3;
                        *(float2*)(pr0 + nt * 8 + 2 * t) = make_float2(f2tf(p0), f2tf(p1));
                        *(float2*)(pr1 + nt * 8 + 2 * t) = make_float2(f2tf(p2), f2tf(p3));
                    }
                }
                __syncwarp();

                #pragma unroll
                for (int kc = 0; kc < 4; kc++) {
                    const int kr = ch * 32 + kc * 8;
                    uint32_t a[2][4];
                    #pragma unroll
                    for (int mi = 0; mi < 2; mi++) {
                        const float* p0 = Pw + (mi * 16 + g) * PSS + kr + t;
                        const float* p1 = p0 + 8 * PSS;
                        a[mi][0] = __float_as_uint(p0[0]);
                        a[mi][1] = __float_as_uint(p1[0]);
                        a[mi][2] = __float_as_uint(p0[4]);
                        a[mi][3] = __float_as_uint(p1[4]);
                    }
                    const float* vb0 = Vs + (kr + t) * VSS + g;
                    const float* vb1 = Vs + (kr + t + 4) * VSS + g;
                    #pragma unroll
                    for (int nt = 0; nt < 8; nt++) {
                        uint32_t b0 = __float_as_uint(vb0[nt * 8]);
                        uint32_t b1 = __float_as_uint(vb1[nt * 8]);
                        mma_tf32(o[0][nt], a[0][0], a[0][1], a[0][2], a[0][3], b0, b1);
                        mma_tf32(o[1][nt], a[1][0], a[1][1], a[1][2], a[1][3], b0, b1);
                    }
                }
                __syncwarp();
            } // ch
        } // kt

        #pragma unroll
        for (int mi = 0; mi < 2; mi++) {
            float l0 = ll[mi][0], l1 = ll[mi][1];
            l0 += __shfl_xor_sync(0xffffffffu, l0, 1);
            l0 += __shfl_xor_sync(0xffffffffu, l0, 2);
            l1 += __shfl_xor_sync(0xffffffffu, l1, 1);
            l1 += __shfl_xor_sync(0xffffffffu, l1, 2);
            const float i0 = 1.0f / l0, i1 = 1.0f / l1;

            float* oa = O + (tok0 + r0 + mi * 16 + g) * DMODEL + h * HD;
            float* ob = oa + 8 * DMODEL;
            #pragma unroll
            for (int nt = 0; nt < 8; nt++) {
                *(float2*)(oa + nt * 8 + 2 * t) =
                    make_float2(o[mi][nt][0] * i0, o[mi][nt][1] * i0);
                *(float2*)(ob + nt * 8 + 2 * t) =
                    make_float2(o[mi][nt][2] * i1, o[mi][nt][3] * i1);
            }
        }
    } // pass
}

// ---------------------------------------------------------------------------
// Launch
// ---------------------------------------------------------------------------
extern "C" void kernel_launch(void* const* d_in, const int* in_sizes, int n_in,
                              void* d_out, int out_size)
{
    const float* x   = (const float*)d_in[0];
    const float* W_q = (const float*)d_in[1];
    const float* W_k = (const float*)d_in[2];
    const float* W_v = (const float*)d_in[3];
    const float* W_o = (const float*)d_in[4];
    float* out = (float*)d_out;

    float *Qp, *Kp, *Vp, *Ap;
    cudaGetSymbolAddress((void**)&Qp, g_Q);
    cudaGetSymbolAddress((void**)&Kp, g_K);
    cudaGetSymbolAddress((void**)&Vp, g_V);
    cudaGetSymbolAddress((void**)&Ap, g_A);

    uint32_t *xh, *xl, *ah, *al;
    uint32_t *wqh, *wql, *wkh, *wkl, *wvh, *wvl, *woh, *wol;
    cudaGetSymbolAddress((void**)&xh,  g_xh);  cudaGetSymbolAddress((void**)&xl,  g_xl);
    cudaGetSymbolAddress((void**)&ah,  g_ah);  cudaGetSymbolAddress((void**)&al,  g_al);
    cudaGetSymbolAddress((void**)&wqh, g_wqh); cudaGetSymbolAddress((void**)&wql, g_wql);
    cudaGetSymbolAddress((void**)&wkh, g_wkh); cudaGetSymbolAddress((void**)&wkl, g_wkl);
    cudaGetSymbolAddress((void**)&wvh, g_wvh); cudaGetSymbolAddress((void**)&wvl, g_wvl);
    cudaGetSymbolAddress((void**)&woh, g_woh); cudaGetSymbolAddress((void**)&wol, g_wol);

    cudaFuncSetAttribute(gemm_bf16p, cudaFuncAttributeMaxDynamicSharedMemorySize, GEMM_SMEM);
    cudaFuncSetAttribute(attn_mma2, cudaFuncAttributeMaxDynamicSharedMemorySize, ATTN_SMEM);

    const int xw = NT * KWRD;        // 2M words
    const int ww = KWRD * DMODEL;    // 512K words

    split_rows<<<(xw + 255) / 256, 256>>>(x, xh, xl, xw);
    dim3 wgrd((ww + 255) / 256, 4);
    split_cols4<<<wgrd, 256>>>(W_q, W_k, W_v, W_o,
                               wqh, wql, wkh, wkl, wvh, wvl, woh, wol,
                               DMODEL, ww);

    // Fused Q/K/V projections: grid.z selects the weight/output
    dim3 qkvgrd(DMODEL / 128, NT / 128, 3);   // (8, 32, 3) = 768 blocks
    gemm_bf16p<<<qkvgrd, 128, GEMM_SMEM>>>(
        xh, xl,
        wqh, wql, Qp,
        wkh, wkl, Kp,
        wvh, wvl, Vp,
        DMODEL, DMODEL, 1);

    dim3 agrd(8, NHEAD, BATCH);
    attn_mma2<<<agrd, 128, ATTN_SMEM>>>(Qp, Kp, Vp, Ap);

    split_rows<<<(xw + 255) / 256, 256>>>(Ap, ah, al, xw);
    dim3 ogrd(DMODEL / 128, NT / 128, 1);
    gemm_bf16p<<<ogrd, 128, GEMM_SMEM>>>(
        ah, al,
        woh, wol, out,
        woh, wol, out,
        woh, wol, out,
        DMODEL, DMODEL, 0);
}